// round 9
// baseline (speedup 1.0000x reference)
#include <cuda_runtime.h>
#include <math.h>
#include <stdint.h>

#define R 1024
#define CIN 256
#define CHID 32
#define NH 8
#define CZ 128
#define HD 256   // NH*CHID
#define NSPLIT 8

// Scratch (static device globals — no runtime allocation)
__device__ float g_mn[R * CIN];
__device__ float g_q[R * HD];
__device__ float g_k[R * HD];
__device__ float g_v[R * HD];
__device__ float g_gw[R * HD];
__device__ float g_bias[(size_t)NH * R * R];   // 32 MB, layout [h][i][j]
__device__ float g_o[R * HD];
__device__ float g_pm[NSPLIT * NH * R];
__device__ float g_pl[NSPLIT * NH * R];
__device__ float g_po[(size_t)NSPLIT * NH * R * CHID];

// ---- packed f32x2 helpers (FFMA2 — only reachable via PTX) ----------------
__device__ __forceinline__ unsigned long long fma2(unsigned long long a,
                                                   unsigned long long b,
                                                   unsigned long long c) {
    unsigned long long d;
    asm("fma.rn.f32x2 %0, %1, %2, %3;" : "=l"(d) : "l"(a), "l"(b), "l"(c));
    return d;
}
__device__ __forceinline__ unsigned long long add2(unsigned long long a,
                                                   unsigned long long b) {
    unsigned long long d;
    asm("add.rn.f32x2 %0, %1, %2;" : "=l"(d) : "l"(a), "l"(b));
    return d;
}
__device__ __forceinline__ float2 unpk2(unsigned long long v) {
    float2 r;
    asm("mov.b64 {%0, %1}, %2;" : "=f"(r.x), "=f"(r.y) : "l"(v));
    return r;
}
__device__ __forceinline__ unsigned long long pk2(float a, float b) {
    unsigned long long d;
    asm("mov.b64 %0, {%1, %2};" : "=l"(d) : "f"(a), "f"(b));
    return d;
}
__device__ __forceinline__ void cpa16(uint32_t dst, const void* src) {
    asm volatile("cp.async.cg.shared.global [%0], [%1], 16;" :: "r"(dst), "l"(src));
}
__device__ __forceinline__ void cpa_commit() {
    asm volatile("cp.async.commit_group;" ::: "memory");
}
template <int N>
__device__ __forceinline__ void cpa_wait() {
    asm volatile("cp.async.wait_group %0;" :: "n"(N) : "memory");
}

// ---------------------------------------------------------------------------
// K1: mn = LayerNorm(m) * w + b
// ---------------------------------------------------------------------------
__global__ void k_lnm(const float* __restrict__ m,
                      const float* __restrict__ w,
                      const float* __restrict__ b) {
    int row = blockIdx.x;
    int c = threadIdx.x;
    float x = m[row * CIN + c];
    float s = x, ss = x * x;
    __shared__ float red[16];
    #pragma unroll
    for (int o = 16; o > 0; o >>= 1) {
        s  += __shfl_xor_sync(0xffffffffu, s, o);
        ss += __shfl_xor_sync(0xffffffffu, ss, o);
    }
    int lane = c & 31, wid = c >> 5;
    if (lane == 0) { red[wid] = s; red[wid + 8] = ss; }
    __syncthreads();
    if (c == 0) {
        float s2 = 0.f, ss2 = 0.f;
        #pragma unroll
        for (int i = 0; i < 8; i++) { s2 += red[i]; ss2 += red[i + 8]; }
        red[0] = s2; red[8] = ss2;
    }
    __syncthreads();
    float mu  = red[0] * (1.0f / CIN);
    float var = red[8] * (1.0f / CIN) - mu * mu;
    float rs  = rsqrtf(var + 1e-5f);
    g_mn[row * CIN + c] = (x - mu) * rs * w[c] + b[c];
}

// ---------------------------------------------------------------------------
// K2: Q,K,V,Gw = mn @ {Wq,Wk,Wv,Wg}
// ---------------------------------------------------------------------------
__global__ void k_qkvg(const float* __restrict__ Wq, const float* __restrict__ Wk,
                       const float* __restrict__ Wv, const float* __restrict__ Wg) {
    const float* W;
    float* out;
    float scale = 1.0f;
    int mz = blockIdx.z;
    if (mz == 0)      { W = Wq; out = g_q; scale = 0.17677669529663687f; }
    else if (mz == 1) { W = Wk; out = g_k; }
    else if (mz == 2) { W = Wv; out = g_v; }
    else              { W = Wg; out = g_gw; }

    int r0 = blockIdx.y * 64, c0 = blockIdx.x * 64;
    __shared__ float As[32][72];
    __shared__ float Bs[32][72];
    int tid = threadIdx.x;
    int tr = tid >> 4, tc = tid & 15;
    float acc[4][4] = {};

    for (int k0 = 0; k0 < CIN; k0 += 32) {
        #pragma unroll
        for (int t = 0; t < 8; t++) {
            int idx = tid + t * 256;
            int r = idx >> 5, kk = idx & 31;
            As[kk][r] = g_mn[(r0 + r) * CIN + k0 + kk];
        }
        #pragma unroll
        for (int t = 0; t < 8; t++) {
            int idx = tid + t * 256;
            int kk = idx >> 6, cc = idx & 63;
            Bs[kk][cc] = W[(k0 + kk) * HD + c0 + cc];
        }
        __syncthreads();
        #pragma unroll
        for (int kk = 0; kk < 32; kk++) {
            float4 a4 = *(const float4*)&As[kk][4 * tr];
            float4 b4 = *(const float4*)&Bs[kk][4 * tc];
            float av[4] = {a4.x, a4.y, a4.z, a4.w};
            float bv[4] = {b4.x, b4.y, b4.z, b4.w};
            #pragma unroll
            for (int rr = 0; rr < 4; rr++)
                #pragma unroll
                for (int cc = 0; cc < 4; cc++)
                    acc[rr][cc] += av[rr] * bv[cc];
        }
        __syncthreads();
    }
    #pragma unroll
    for (int rr = 0; rr < 4; rr++) {
        float4 o4 = make_float4(acc[rr][0] * scale, acc[rr][1] * scale,
                                acc[rr][2] * scale, acc[rr][3] * scale);
        *(float4*)&out[(r0 + 4 * tr + rr) * HD + c0 + 4 * tc] = o4;
    }
}

// ---------------------------------------------------------------------------
// K3 (v8): warp-cooperative rows, weights in REGISTERS, z cp.async-staged.
// Lane = (hp = lane>>3, g = lane&7). Lane owns heads {2hp,2hp+1} and
// c-positions {32u+4g..+3 : u<4} -> 16 packed f32x2 weight regs, built once.
// Warp processes one row at a time: 4 broadcast LDS.128 + 32 f32x2 ops +
// 12 butterfly shuffles (xor 1,2,4 over g). smem crossbar traffic/row drops
// 4.6KB -> 512B (9x less than thread-per-row).
// Tile 64 rows x 128 f (stride 132: halves at 0/68). 128 thr (4 warps, 16
// rows each), single buffer, 4 tiles/block. ~36KB -> 6 blocks/SM, 24 w/SM.
// grid (4, 1024).
// ---------------------------------------------------------------------------
#define BT_ROWS 64
#define BT_STRIDE 132     // words per row in smem
#define BT_TILES 4
#define SB_S 65

__global__ __launch_bounds__(128) void k_bias(const float* __restrict__ z,
                                              const float* __restrict__ lnw,
                                              const float* __restrict__ lnb,
                                              const float* __restrict__ Wz) {
    __shared__ __align__(16) float zs[BT_ROWS * BT_STRIDE];
    __shared__ float sb[NH * SB_S];
    __shared__ float s_cs[NH], s_cb[NH];

    int tid = threadIdx.x;
    int lane = tid & 31, w = tid >> 5;
    int g = lane & 7, hp = lane >> 3;
    int h0 = 2 * hp, h1 = h0 + 1;
    int i  = blockIdx.y;
    int jb = blockIdx.x * (BT_ROWS * BT_TILES);   // 256-j strip

    const float* zstrip = z + ((size_t)i * R + jb) * CZ;
    uint32_t zs_base = (uint32_t)__cvta_generic_to_shared(&zs[0]);

    // ---- per-lane packed weights (live in registers for the whole kernel)
    unsigned long long wA[4][2], wB[4][2];
    #pragma unroll
    for (int u = 0; u < 4; u++) {
        int c = 32 * u + 4 * g;
        float l0 = lnw[c], l1 = lnw[c + 1], l2 = lnw[c + 2], l3 = lnw[c + 3];
        wA[u][0] = pk2(l0 * Wz[(c + 0) * NH + h0], l1 * Wz[(c + 1) * NH + h0]);
        wA[u][1] = pk2(l2 * Wz[(c + 2) * NH + h0], l3 * Wz[(c + 3) * NH + h0]);
        wB[u][0] = pk2(l0 * Wz[(c + 0) * NH + h1], l1 * Wz[(c + 1) * NH + h1]);
        wB[u][1] = pk2(l2 * Wz[(c + 2) * NH + h1], l3 * Wz[(c + 3) * NH + h1]);
    }
    if (tid < NH) {
        float cs = 0.f, cb = 0.f;
        #pragma unroll 4
        for (int c = 0; c < CZ; c++) {
            float wv = Wz[c * NH + tid];
            cs += lnw[c] * wv;
            cb += lnb[c] * wv;
        }
        s_cs[tid] = cs; s_cb[tid] = cb;
    }
    __syncthreads();
    float csh0 = s_cs[h0], csh1 = s_cs[h1];
    float cbh0 = s_cb[h0], cbh1 = s_cb[h1];

    // ---- main loop over 4 tiles, single buffer (inter-block overlap)
    for (int tt = 0; tt < BT_TILES; tt++) {
        const float* src = zstrip + (size_t)tt * BT_ROWS * CZ;
        #pragma unroll
        for (int k = 0; k < 16; k++) {
            int idx = tid + k * 128;           // 0..2047 float4 slots
            int row = idx >> 5, s4 = idx & 31;
            uint32_t dw = (uint32_t)(row * BT_STRIDE + s4 * 4 + ((s4 >= 16) ? 4 : 0));
            cpa16(zs_base + dw * 4, src + row * CZ + s4 * 4);
        }
        cpa_commit();
        cpa_wait<0>();
        __syncthreads();

        // ---- compute: warp w owns rows 16w..16w+15; whole warp per row
        #pragma unroll 2
        for (int r = 0; r < 16; r++) {
            int row = w * 16 + r;
            const float* zr = &zs[row * BT_STRIDE];
            // els: u=0 -> word 4g, u=1 -> 32+4g, u=2 -> 68+4g, u=3 -> 100+4g
            ulonglong2 z0 = *(const ulonglong2*)(zr + 4 * g);
            ulonglong2 z1 = *(const ulonglong2*)(zr + 32 + 4 * g);
            ulonglong2 z2 = *(const ulonglong2*)(zr + 68 + 4 * g);
            ulonglong2 z3 = *(const ulonglong2*)(zr + 100 + 4 * g);

            unsigned long long aS, aQ = 0ull, d0 = 0ull, d1 = 0ull;
            aS = add2(add2(z0.x, z0.y), add2(z1.x, z1.y));
            aS = add2(aS, add2(add2(z2.x, z2.y), add2(z3.x, z3.y)));
            aQ = fma2(z0.x, z0.x, aQ); aQ = fma2(z0.y, z0.y, aQ);
            aQ = fma2(z1.x, z1.x, aQ); aQ = fma2(z1.y, z1.y, aQ);
            aQ = fma2(z2.x, z2.x, aQ); aQ = fma2(z2.y, z2.y, aQ);
            aQ = fma2(z3.x, z3.x, aQ); aQ = fma2(z3.y, z3.y, aQ);
            d0 = fma2(z0.x, wA[0][0], d0); d0 = fma2(z0.y, wA[0][1], d0);
            d1 = fma2(z0.x, wB[0][0], d1); d1 = fma2(z0.y, wB[0][1], d1);
            d0 = fma2(z1.x, wA[1][0], d0); d0 = fma2(z1.y, wA[1][1], d0);
            d1 = fma2(z1.x, wB[1][0], d1); d1 = fma2(z1.y, wB[1][1], d1);
            d0 = fma2(z2.x, wA[2][0], d0); d0 = fma2(z2.y, wA[2][1], d0);
            d1 = fma2(z2.x, wB[2][0], d1); d1 = fma2(z2.y, wB[2][1], d1);
            d0 = fma2(z3.x, wA[3][0], d0); d0 = fma2(z3.y, wA[3][1], d0);
            d1 = fma2(z3.x, wB[3][0], d1); d1 = fma2(z3.y, wB[3][1], d1);

            float2 eS = unpk2(aS), eQ = unpk2(aQ), e0 = unpk2(d0), e1 = unpk2(d1);
            float fs = eS.x + eS.y, fq = eQ.x + eQ.y;
            float f0 = e0.x + e0.y, f1 = e1.x + e1.y;
            #pragma unroll
            for (int o = 1; o <= 4; o <<= 1) {
                fs += __shfl_xor_sync(0xffffffffu, fs, o);
                fq += __shfl_xor_sync(0xffffffffu, fq, o);
                f0 += __shfl_xor_sync(0xffffffffu, f0, o);
                f1 += __shfl_xor_sync(0xffffffffu, f1, o);
            }
            float mu  = fs * (1.0f / CZ);
            float var = fq * (1.0f / CZ) - mu * mu;
            float rs  = rsqrtf(var + 1e-5f);
            if (g == 0) {
                sb[h0 * SB_S + row] = rs * (f0 - mu * csh0) + cbh0;
                sb[h1 * SB_S + row] = rs * (f1 - mu * csh1) + cbh1;
            }
        }
        __syncthreads();

        // ---- coalesced flush: 512 floats, 64-float contiguous per head
        size_t jt0 = (size_t)jb + tt * BT_ROWS;
        #pragma unroll
        for (int k = 0; k < 4; k++) {
            int idx = tid + k * 128;
            int hh = idx >> 6, jj = idx & 63;
            g_bias[((size_t)hh * R + i) * R + jt0 + jj] = sb[hh * SB_S + jj];
        }
        __syncthreads();
    }
}

// ---------------------------------------------------------------------------
// K4: flash attention with additive bias, SPLIT over j (NSPLIT=8).
// grid (16 q-tiles, 8 heads, 8 j-splits), 256 threads; 128 j per block.
// ---------------------------------------------------------------------------
__global__ void k_attn() {
    int h   = blockIdx.y;
    int q0  = blockIdx.x * 64;
    int zsp = blockIdx.z;
    int tid = threadIdx.x;
    int tr = tid >> 4, tc = tid & 15;

    __shared__ float qT[32][72];
    __shared__ float kT[32][72];
    __shared__ float vs[64][36];
    __shared__ float ps[64][68];
    __shared__ float m_s[64], l_s[64], f_s[64];

    #pragma unroll
    for (int t = 0; t < 8; t++) {
        int idx = tid + t * 256;
        int r = idx >> 5, d = idx & 31;
        qT[d][r] = g_q[(q0 + r) * HD + h * CHID + d];
    }
    if (tid < 64) { m_s[tid] = -1e30f; l_s[tid] = 0.f; }

    float o[4][2] = {};

    for (int jt = 0; jt < 2; jt++) {
        int j0 = zsp * 128 + jt * 64;
        __syncthreads();
        #pragma unroll
        for (int t = 0; t < 8; t++) {
            int idx = tid + t * 256;
            int r = idx >> 5, d = idx & 31;
            kT[d][r] = g_k[(j0 + r) * HD + h * CHID + d];
            vs[r][d] = g_v[(j0 + r) * HD + h * CHID + d];
        }
        __syncthreads();

        float s[4][4];
        #pragma unroll
        for (int rr = 0; rr < 4; rr++) {
            float4 b4 = *(const float4*)&g_bias[((size_t)h * R + q0 + 4 * tr + rr) * R + j0 + 4 * tc];
            s[rr][0] = b4.x; s[rr][1] = b4.y; s[rr][2] = b4.z; s[rr][3] = b4.w;
        }
        #pragma unroll
        for (int kk = 0; kk < 32; kk++) {
            float4 a4 = *(const float4*)&qT[kk][4 * tr];
            float4 b4 = *(const float4*)&kT[kk][4 * tc];
            float av[4] = {a4.x, a4.y, a4.z, a4.w};
            float bv[4] = {b4.x, b4.y, b4.z, b4.w};
            #pragma unroll
            for (int rr = 0; rr < 4; rr++)
                #pragma unroll
                for (int cc = 0; cc < 4; cc++)
                    s[rr][cc] += av[rr] * bv[cc];
        }
        #pragma unroll
        for (int rr = 0; rr < 4; rr++)
            *(float4*)&ps[4 * tr + rr][4 * tc] =
                make_float4(s[rr][0], s[rr][1], s[rr][2], s[rr][3]);
        __syncthreads();

        {
            int row = tid >> 2, p = tid & 3;
            float mo = m_s[row];
            float mc = -1e30f;
            #pragma unroll
            for (int c = 0; c < 16; c += 4) {
                float4 v = *(const float4*)&ps[row][p * 16 + c];
                mc = fmaxf(mc, fmaxf(fmaxf(v.x, v.y), fmaxf(v.z, v.w)));
            }
            mc = fmaxf(mc, __shfl_xor_sync(0xffffffffu, mc, 1));
            mc = fmaxf(mc, __shfl_xor_sync(0xffffffffu, mc, 2));
            float mn2 = fmaxf(mo, mc);
            float l = 0.f;
            #pragma unroll
            for (int c = 0; c < 16; c += 4) {
                float4 v = *(const float4*)&ps[row][p * 16 + c];
                v.x = __expf(v.x - mn2); v.y = __expf(v.y - mn2);
                v.z = __expf(v.z - mn2); v.w = __expf(v.w - mn2);
                *(float4*)&ps[row][p * 16 + c] = v;
                l += v.x + v.y + v.z + v.w;
            }
            l += __shfl_xor_sync(0xffffffffu, l, 1);
            l += __shfl_xor_sync(0xffffffffu, l, 2);
            if (p == 0) {
                float f = __expf(mo - mn2);
                f_s[row] = f;
                l_s[row] = l_s[row] * f + l;
                m_s[row] = mn2;
            }
        }
        __syncthreads();

        float fr[4];
        #pragma unroll
        for (int rr = 0; rr < 4; rr++) fr[rr] = f_s[4 * tr + rr];
        #pragma unroll
        for (int rr = 0; rr < 4; rr++) { o[rr][0] *= fr[rr]; o[rr][1] *= fr[rr]; }

        #pragma unroll
        for (int j = 0; j < 64; j += 4) {
            float4 pv[4];
            #pragma unroll
            for (int rr = 0; rr < 4; rr++)
                pv[rr] = *(const float4*)&ps[4 * tr + rr][j];
            float2 vv[4];
            #pragma unroll
            for (int e = 0; e < 4; e++)
                vv[e] = *(const float2*)&vs[j + e][2 * tc];
            #pragma unroll
            for (int rr = 0; rr < 4; rr++) {
                o[rr][0] += pv[rr].x * vv[0].x; o[rr][1] += pv[rr].x * vv[0].y;
                o[rr][0] += pv[rr].y * vv[1].x; o[rr][1] += pv[rr].y * vv[1].y;
                o[rr][0] += pv[rr].z * vv[2].x; o[rr][1] += pv[rr].z * vv[2].y;
                o[rr][0] += pv[rr].w * vv[3].x; o[rr][1] += pv[rr].w * vv[3].y;
            }
        }
    }

    int base = (zsp * NH + h) * R + q0;
    #pragma unroll
    for (int rr = 0; rr < 4; rr++) {
        g_po[(size_t)(base + 4 * tr + rr) * CHID + 2 * tc + 0] = o[rr][0];
        g_po[(size_t)(base + 4 * tr + rr) * CHID + 2 * tc + 1] = o[rr][1];
    }
    __syncthreads();
    if (tid < 64) {
        g_pm[base + tid] = m_s[tid];
        g_pl[base + tid] = l_s[tid];
    }
}

// ---------------------------------------------------------------------------
// K4b: merge split-j partials -> g_o
// ---------------------------------------------------------------------------
__global__ void k_merge() {
    int idx = blockIdx.x * 256 + threadIdx.x;      // over NH*R*CHID = 262144
    int d = idx & (CHID - 1);
    int q = (idx >> 5) & (R - 1);
    int h = idx >> 15;

    float mv[NSPLIT];
    float M = -1e30f;
    #pragma unroll
    for (int s2 = 0; s2 < NSPLIT; s2++) {
        mv[s2] = g_pm[(s2 * NH + h) * R + q];
        M = fmaxf(M, mv[s2]);
    }
    float L = 0.f, ov = 0.f;
    #pragma unroll
    for (int s2 = 0; s2 < NSPLIT; s2++) {
        float e = __expf(mv[s2] - M);
        L  += g_pl[(s2 * NH + h) * R + q] * e;
        ov += g_po[(size_t)((s2 * NH + h) * R + q) * CHID + d] * e;
    }
    g_o[q * HD + h * CHID + d] = ov / L;
}

// ---------------------------------------------------------------------------
// K5: out = (o * sigmoid(gw)) @ Wo + bo
// ---------------------------------------------------------------------------
__global__ void k_out(const float* __restrict__ Wo,
                      const float* __restrict__ bo,
                      float* __restrict__ out) {
    int r0 = blockIdx.y * 64, c0 = blockIdx.x * 64;
    __shared__ float As[32][72];
    __shared__ float Bs[32][72];
    int tid = threadIdx.x;
    int tr = tid >> 4, tc = tid & 15;
    float acc[4][4] = {};

    for (int k0 = 0; k0 < HD; k0 += 32) {
        #pragma unroll
        for (int t = 0; t < 8; t++) {
            int idx = tid + t * 256;
            int r = idx >> 5, kk = idx & 31;
            int gi = (r0 + r) * HD + k0 + kk;
            float gate = 1.0f / (1.0f + __expf(-g_gw[gi]));
            As[kk][r] = g_o[gi] * gate;
        }
        #pragma unroll
        for (int t = 0; t < 8; t++) {
            int idx = tid + t * 256;
            int kk = idx >> 6, cc = idx & 63;
            Bs[kk][cc] = Wo[(k0 + kk) * CIN + c0 + cc];
        }
        __syncthreads();
        #pragma unroll
        for (int kk = 0; kk < 32; kk++) {
            float4 a4 = *(const float4*)&As[kk][4 * tr];
            float4 b4 = *(const float4*)&Bs[kk][4 * tc];
            float av[4] = {a4.x, a4.y, a4.z, a4.w};
            float bv[4] = {b4.x, b4.y, b4.z, b4.w};
            #pragma unroll
            for (int rr = 0; rr < 4; rr++)
                #pragma unroll
                for (int cc = 0; cc < 4; cc++)
                    acc[rr][cc] += av[rr] * bv[cc];
        }
        __syncthreads();
    }
    #pragma unroll
    for (int rr = 0; rr < 4; rr++) {
        int c = c0 + 4 * tc;
        float4 o4 = make_float4(acc[rr][0] + bo[c + 0], acc[rr][1] + bo[c + 1],
                                acc[rr][2] + bo[c + 2], acc[rr][3] + bo[c + 3]);
        *(float4*)&out[(r0 + 4 * tr + rr) * CIN + c] = o4;
    }
}

// ---------------------------------------------------------------------------
extern "C" void kernel_launch(void* const* d_in, const int* in_sizes, int n_in,
                              void* d_out, int out_size) {
    const float* m      = (const float*)d_in[0];
    const float* z      = (const float*)d_in[1];
    const float* ln_m_w = (const float*)d_in[2];
    const float* ln_m_b = (const float*)d_in[3];
    const float* ln_z_w = (const float*)d_in[4];
    const float* ln_z_b = (const float*)d_in[5];
    const float* Wz     = (const float*)d_in[6];
    const float* Wq     = (const float*)d_in[7];
    const float* Wk     = (const float*)d_in[8];
    const float* Wv     = (const float*)d_in[9];
    const float* Wg     = (const float*)d_in[10];
    // d_in[11] = bg (unused by reference)
    const float* Wo     = (const float*)d_in[12];
    const float* bo     = (const float*)d_in[13];
    float* out = (float*)d_out;

    k_lnm<<<R, 256>>>(m, ln_m_w, ln_m_b);
    k_qkvg<<<dim3(4, 16, 4), 256>>>(Wq, Wk, Wv, Wg);
    k_bias<<<dim3(4, R), 128>>>(z, ln_z_w, ln_z_b, Wz);
    k_attn<<<dim3(16, NH, NSPLIT), 256>>>();
    k_merge<<<NH * R * CHID / 256, 256>>>();
    k_out<<<dim3(4, 16), 256>>>(Wo, bo, out);
}

// round 10
// speedup vs baseline: 1.1482x; 1.1482x over previous
#include <cuda_runtime.h>
#include <math.h>
#include <stdint.h>

#define R 1024
#define CIN 256
#define CHID 32
#define NH 8
#define CZ 128
#define HD 256   // NH*CHID
#define NSPLIT 8

// Scratch (static device globals — no runtime allocation)
__device__ float g_mn[R * CIN];
__device__ float g_q[R * HD];
__device__ float g_k[R * HD];
__device__ float g_v[R * HD];
__device__ float g_gw[R * HD];
__device__ float g_bias[(size_t)NH * R * R];   // 32 MB, layout [h][i][j]
__device__ float g_o[R * HD];
__device__ float g_pm[NSPLIT * NH * R];
__device__ float g_pl[NSPLIT * NH * R];
__device__ float g_po[(size_t)NSPLIT * NH * R * CHID];

// ---- packed f32x2 helpers (FFMA2 — only reachable via PTX) ----------------
__device__ __forceinline__ unsigned long long fma2(unsigned long long a,
                                                   unsigned long long b,
                                                   unsigned long long c) {
    unsigned long long d;
    asm("fma.rn.f32x2 %0, %1, %2, %3;" : "=l"(d) : "l"(a), "l"(b), "l"(c));
    return d;
}
__device__ __forceinline__ unsigned long long add2(unsigned long long a,
                                                   unsigned long long b) {
    unsigned long long d;
    asm("add.rn.f32x2 %0, %1, %2;" : "=l"(d) : "l"(a), "l"(b));
    return d;
}
__device__ __forceinline__ float2 unpk2(unsigned long long v) {
    float2 r;
    asm("mov.b64 {%0, %1}, %2;" : "=f"(r.x), "=f"(r.y) : "l"(v));
    return r;
}
__device__ __forceinline__ unsigned long long pk2(float a, float b) {
    unsigned long long d;
    asm("mov.b64 %0, {%1, %2};" : "=l"(d) : "f"(a), "f"(b));
    return d;
}
__device__ __forceinline__ void cpa16(uint32_t dst, const void* src) {
    asm volatile("cp.async.cg.shared.global [%0], [%1], 16;" :: "r"(dst), "l"(src));
}
__device__ __forceinline__ void cpa_commit() {
    asm volatile("cp.async.commit_group;" ::: "memory");
}
template <int N>
__device__ __forceinline__ void cpa_wait() {
    asm volatile("cp.async.wait_group %0;" :: "n"(N) : "memory");
}

// ---------------------------------------------------------------------------
// K1: mn = LayerNorm(m) * w + b
// ---------------------------------------------------------------------------
__global__ void k_lnm(const float* __restrict__ m,
                      const float* __restrict__ w,
                      const float* __restrict__ b) {
    int row = blockIdx.x;
    int c = threadIdx.x;
    float x = m[row * CIN + c];
    float s = x, ss = x * x;
    __shared__ float red[16];
    #pragma unroll
    for (int o = 16; o > 0; o >>= 1) {
        s  += __shfl_xor_sync(0xffffffffu, s, o);
        ss += __shfl_xor_sync(0xffffffffu, ss, o);
    }
    int lane = c & 31, wid = c >> 5;
    if (lane == 0) { red[wid] = s; red[wid + 8] = ss; }
    __syncthreads();
    if (c == 0) {
        float s2 = 0.f, ss2 = 0.f;
        #pragma unroll
        for (int i = 0; i < 8; i++) { s2 += red[i]; ss2 += red[i + 8]; }
        red[0] = s2; red[8] = ss2;
    }
    __syncthreads();
    float mu  = red[0] * (1.0f / CIN);
    float var = red[8] * (1.0f / CIN) - mu * mu;
    float rs  = rsqrtf(var + 1e-5f);
    g_mn[row * CIN + c] = (x - mu) * rs * w[c] + b[c];
}

// ---------------------------------------------------------------------------
// K2: Q,K,V,Gw = mn @ {Wq,Wk,Wv,Wg}
// ---------------------------------------------------------------------------
__global__ void k_qkvg(const float* __restrict__ Wq, const float* __restrict__ Wk,
                       const float* __restrict__ Wv, const float* __restrict__ Wg) {
    const float* W;
    float* out;
    float scale = 1.0f;
    int mz = blockIdx.z;
    if (mz == 0)      { W = Wq; out = g_q; scale = 0.17677669529663687f; }
    else if (mz == 1) { W = Wk; out = g_k; }
    else if (mz == 2) { W = Wv; out = g_v; }
    else              { W = Wg; out = g_gw; }

    int r0 = blockIdx.y * 64, c0 = blockIdx.x * 64;
    __shared__ float As[32][72];
    __shared__ float Bs[32][72];
    int tid = threadIdx.x;
    int tr = tid >> 4, tc = tid & 15;
    float acc[4][4] = {};

    for (int k0 = 0; k0 < CIN; k0 += 32) {
        #pragma unroll
        for (int t = 0; t < 8; t++) {
            int idx = tid + t * 256;
            int r = idx >> 5, kk = idx & 31;
            As[kk][r] = g_mn[(r0 + r) * CIN + k0 + kk];
        }
        #pragma unroll
        for (int t = 0; t < 8; t++) {
            int idx = tid + t * 256;
            int kk = idx >> 6, cc = idx & 63;
            Bs[kk][cc] = W[(k0 + kk) * HD + c0 + cc];
        }
        __syncthreads();
        #pragma unroll
        for (int kk = 0; kk < 32; kk++) {
            float4 a4 = *(const float4*)&As[kk][4 * tr];
            float4 b4 = *(const float4*)&Bs[kk][4 * tc];
            float av[4] = {a4.x, a4.y, a4.z, a4.w};
            float bv[4] = {b4.x, b4.y, b4.z, b4.w};
            #pragma unroll
            for (int rr = 0; rr < 4; rr++)
                #pragma unroll
                for (int cc = 0; cc < 4; cc++)
                    acc[rr][cc] += av[rr] * bv[cc];
        }
        __syncthreads();
    }
    #pragma unroll
    for (int rr = 0; rr < 4; rr++) {
        float4 o4 = make_float4(acc[rr][0] * scale, acc[rr][1] * scale,
                                acc[rr][2] * scale, acc[rr][3] * scale);
        *(float4*)&out[(r0 + 4 * tr + rr) * HD + c0 + 4 * tc] = o4;
    }
}

// ---------------------------------------------------------------------------
// K3 (v9): register-tiled 2 rows x 4 heads per thread, zero shuffles.
// Tile: 128 rows x 128 floats (stride 132: halves at 0/68). 128 threads:
// thread = (hg = tid>>6, rg = tid&63) owns rows {rg, rg+64}, heads 4hg..4hg+3.
// Per 4-el chunk: 2 z-LDS.128 (conflict-free) + 4 w-LDS.128 (warp-broadcast,
// hg uniform per warp) + 16 dot-FFMA2 + 6 sum/sumsq ops.
// 6 warp-LDS per row (vs 9 in thread-per-row) -> crossbar ~93us.
// Direct coalesced bias stores (128B per (h,row) per warp), no staging.
// smem: 67.6KB tile + 4KB weight table -> 3 blocks/SM, 12 warps/SM.
// grid (8, 1024), 128 threads, single buffer (inter-block overlap).
// ---------------------------------------------------------------------------
#define BT_ROWS 128
#define BT_STRIDE 132     // words per row in smem

__global__ __launch_bounds__(128) void k_bias(const float* __restrict__ z,
                                              const float* __restrict__ lnw,
                                              const float* __restrict__ lnb,
                                              const float* __restrict__ Wz) {
    __shared__ __align__(16) float zs[BT_ROWS * BT_STRIDE];
    __shared__ __align__(16) unsigned long long ws[32 * 16]; // [u][hg*8 + k*2 + pair]
    __shared__ float s_cs[NH], s_cb[NH];

    int tid = threadIdx.x;
    int hg = tid >> 6;           // head group: heads 4hg..4hg+3 (uniform per warp)
    int rg = tid & 63;           // rows rg and rg+64
    int i  = blockIdx.y;
    int jb = blockIdx.x * BT_ROWS;

    const float* ztile = z + ((size_t)i * R + jb) * CZ;
    uint32_t zs_base = (uint32_t)__cvta_generic_to_shared(&zs[0]);

    // ---- issue tile load immediately (32 x 16B per thread, coalesced)
    #pragma unroll
    for (int k = 0; k < 32; k++) {
        int idx = tid + k * 128;           // 0..4095 float4 slots
        int row = idx >> 5, s4 = idx & 31;
        uint32_t dw = (uint32_t)(row * BT_STRIDE + s4 * 4 + ((s4 >= 16) ? 4 : 0));
        cpa16(zs_base + dw * 4, ztile + row * CZ + s4 * 4);
    }
    cpa_commit();

    // ---- build weight table while loads fly:
    // ws[u][g8*8 + k*2 + p] = pk2(lnw[c]*Wz[c][h], lnw[c+1]*Wz[c+1][h]),
    //   h = 4*g8 + k, c = 4u + 2p.
    #pragma unroll
    for (int e = 0; e < 4; e++) {
        int idx = tid + e * 128;           // 0..511
        int u = idx >> 4, slot = idx & 15;
        int g8 = slot >> 3, k = (slot >> 1) & 3, p = slot & 1;
        int h = 4 * g8 + k;
        int c = 4 * u + 2 * p;
        ws[u * 16 + slot] =
            pk2(lnw[c] * Wz[c * NH + h], lnw[c + 1] * Wz[(c + 1) * NH + h]);
    }
    if (tid < NH) {
        float cs = 0.f, cb = 0.f;
        #pragma unroll 4
        for (int c = 0; c < CZ; c++) {
            float wv = Wz[c * NH + tid];
            cs += lnw[c] * wv;
            cb += lnb[c] * wv;
        }
        s_cs[tid] = cs; s_cb[tid] = cb;
    }

    cpa_wait<0>();
    __syncthreads();

    // ---- compute: 2 rows, 4 heads, full k-range per thread
    const float* zr0 = &zs[rg * BT_STRIDE];
    const float* zr1 = &zs[(rg + 64) * BT_STRIDE];
    unsigned long long aD0[4] = {0ull, 0ull, 0ull, 0ull};  // row0, heads 4hg+0..3
    unsigned long long aD1[4] = {0ull, 0ull, 0ull, 0ull};  // row1
    unsigned long long aS0 = 0ull, aQ0 = 0ull, aS1 = 0ull, aQ1 = 0ull;

    #pragma unroll
    for (int half = 0; half < 2; half++) {
        #pragma unroll 4
        for (int t = 0; t < 16; t++) {
            int u = half * 16 + t;
            int off = half * 68 + 4 * t;
            const ulonglong2* wp = (const ulonglong2*)&ws[u * 16 + hg * 8];
            ulonglong2 w0 = wp[0], w1 = wp[1], w2 = wp[2], w3 = wp[3];
            ulonglong2 za = *(const ulonglong2*)(zr0 + off);
            ulonglong2 zb = *(const ulonglong2*)(zr1 + off);

            aS0 = add2(aS0, add2(za.x, za.y));
            aQ0 = fma2(za.x, za.x, aQ0); aQ0 = fma2(za.y, za.y, aQ0);
            aD0[0] = fma2(za.x, w0.x, aD0[0]); aD0[0] = fma2(za.y, w0.y, aD0[0]);
            aD0[1] = fma2(za.x, w1.x, aD0[1]); aD0[1] = fma2(za.y, w1.y, aD0[1]);
            aD0[2] = fma2(za.x, w2.x, aD0[2]); aD0[2] = fma2(za.y, w2.y, aD0[2]);
            aD0[3] = fma2(za.x, w3.x, aD0[3]); aD0[3] = fma2(za.y, w3.y, aD0[3]);

            aS1 = add2(aS1, add2(zb.x, zb.y));
            aQ1 = fma2(zb.x, zb.x, aQ1); aQ1 = fma2(zb.y, zb.y, aQ1);
            aD1[0] = fma2(zb.x, w0.x, aD1[0]); aD1[0] = fma2(zb.y, w0.y, aD1[0]);
            aD1[1] = fma2(zb.x, w1.x, aD1[1]); aD1[1] = fma2(zb.y, w1.y, aD1[1]);
            aD1[2] = fma2(zb.x, w2.x, aD1[2]); aD1[2] = fma2(zb.y, w2.y, aD1[2]);
            aD1[3] = fma2(zb.x, w3.x, aD1[3]); aD1[3] = fma2(zb.y, w3.y, aD1[3]);
        }
    }

    // ---- epilogue: per-row LN stats + per-head bias, direct coalesced STG
    float csh[4], cbh[4];
    #pragma unroll
    for (int k = 0; k < 4; k++) { csh[k] = s_cs[4 * hg + k]; cbh[k] = s_cb[4 * hg + k]; }

    {
        float2 eS = unpk2(aS0), eQ = unpk2(aQ0);
        float fs = eS.x + eS.y, fq = eQ.x + eQ.y;
        float mu  = fs * (1.0f / CZ);
        float var = fq * (1.0f / CZ) - mu * mu;
        float rs  = rsqrtf(var + 1e-5f);
        size_t j = (size_t)jb + rg;
        #pragma unroll
        for (int k = 0; k < 4; k++) {
            float2 dd = unpk2(aD0[k]);
            g_bias[((size_t)(4 * hg + k) * R + i) * R + j] =
                rs * ((dd.x + dd.y) - mu * csh[k]) + cbh[k];
        }
    }
    {
        float2 eS = unpk2(aS1), eQ = unpk2(aQ1);
        float fs = eS.x + eS.y, fq = eQ.x + eQ.y;
        float mu  = fs * (1.0f / CZ);
        float var = fq * (1.0f / CZ) - mu * mu;
        float rs  = rsqrtf(var + 1e-5f);
        size_t j = (size_t)jb + rg + 64;
        #pragma unroll
        for (int k = 0; k < 4; k++) {
            float2 dd = unpk2(aD1[k]);
            g_bias[((size_t)(4 * hg + k) * R + i) * R + j] =
                rs * ((dd.x + dd.y) - mu * csh[k]) + cbh[k];
        }
    }
}

// ---------------------------------------------------------------------------
// K4: flash attention with additive bias, SPLIT over j (NSPLIT=8).
// grid (16 q-tiles, 8 heads, 8 j-splits), 256 threads; 128 j per block.
// ---------------------------------------------------------------------------
__global__ void k_attn() {
    int h   = blockIdx.y;
    int q0  = blockIdx.x * 64;
    int zsp = blockIdx.z;
    int tid = threadIdx.x;
    int tr = tid >> 4, tc = tid & 15;

    __shared__ float qT[32][72];
    __shared__ float kT[32][72];
    __shared__ float vs[64][36];
    __shared__ float ps[64][68];
    __shared__ float m_s[64], l_s[64], f_s[64];

    #pragma unroll
    for (int t = 0; t < 8; t++) {
        int idx = tid + t * 256;
        int r = idx >> 5, d = idx & 31;
        qT[d][r] = g_q[(q0 + r) * HD + h * CHID + d];
    }
    if (tid < 64) { m_s[tid] = -1e30f; l_s[tid] = 0.f; }

    float o[4][2] = {};

    for (int jt = 0; jt < 2; jt++) {
        int j0 = zsp * 128 + jt * 64;
        __syncthreads();
        #pragma unroll
        for (int t = 0; t < 8; t++) {
            int idx = tid + t * 256;
            int r = idx >> 5, d = idx & 31;
            kT[d][r] = g_k[(j0 + r) * HD + h * CHID + d];
            vs[r][d] = g_v[(j0 + r) * HD + h * CHID + d];
        }
        __syncthreads();

        float s[4][4];
        #pragma unroll
        for (int rr = 0; rr < 4; rr++) {
            float4 b4 = *(const float4*)&g_bias[((size_t)h * R + q0 + 4 * tr + rr) * R + j0 + 4 * tc];
            s[rr][0] = b4.x; s[rr][1] = b4.y; s[rr][2] = b4.z; s[rr][3] = b4.w;
        }
        #pragma unroll
        for (int kk = 0; kk < 32; kk++) {
            float4 a4 = *(const float4*)&qT[kk][4 * tr];
            float4 b4 = *(const float4*)&kT[kk][4 * tc];
            float av[4] = {a4.x, a4.y, a4.z, a4.w};
            float bv[4] = {b4.x, b4.y, b4.z, b4.w};
            #pragma unroll
            for (int rr = 0; rr < 4; rr++)
                #pragma unroll
                for (int cc = 0; cc < 4; cc++)
                    s[rr][cc] += av[rr] * bv[cc];
        }
        #pragma unroll
        for (int rr = 0; rr < 4; rr++)
            *(float4*)&ps[4 * tr + rr][4 * tc] =
                make_float4(s[rr][0], s[rr][1], s[rr][2], s[rr][3]);
        __syncthreads();

        {
            int row = tid >> 2, p = tid & 3;
            float mo = m_s[row];
            float mc = -1e30f;
            #pragma unroll
            for (int c = 0; c < 16; c += 4) {
                float4 v = *(const float4*)&ps[row][p * 16 + c];
                mc = fmaxf(mc, fmaxf(fmaxf(v.x, v.y), fmaxf(v.z, v.w)));
            }
            mc = fmaxf(mc, __shfl_xor_sync(0xffffffffu, mc, 1));
            mc = fmaxf(mc, __shfl_xor_sync(0xffffffffu, mc, 2));
            float mn2 = fmaxf(mo, mc);
            float l = 0.f;
            #pragma unroll
            for (int c = 0; c < 16; c += 4) {
                float4 v = *(const float4*)&ps[row][p * 16 + c];
                v.x = __expf(v.x - mn2); v.y = __expf(v.y - mn2);
                v.z = __expf(v.z - mn2); v.w = __expf(v.w - mn2);
                *(float4*)&ps[row][p * 16 + c] = v;
                l += v.x + v.y + v.z + v.w;
            }
            l += __shfl_xor_sync(0xffffffffu, l, 1);
            l += __shfl_xor_sync(0xffffffffu, l, 2);
            if (p == 0) {
                float f = __expf(mo - mn2);
                f_s[row] = f;
                l_s[row] = l_s[row] * f + l;
                m_s[row] = mn2;
            }
        }
        __syncthreads();

        float fr[4];
        #pragma unroll
        for (int rr = 0; rr < 4; rr++) fr[rr] = f_s[4 * tr + rr];
        #pragma unroll
        for (int rr = 0; rr < 4; rr++) { o[rr][0] *= fr[rr]; o[rr][1] *= fr[rr]; }

        #pragma unroll
        for (int j = 0; j < 64; j += 4) {
            float4 pv[4];
            #pragma unroll
            for (int rr = 0; rr < 4; rr++)
                pv[rr] = *(const float4*)&ps[4 * tr + rr][j];
            float2 vv[4];
            #pragma unroll
            for (int e = 0; e < 4; e++)
                vv[e] = *(const float2*)&vs[j + e][2 * tc];
            #pragma unroll
            for (int rr = 0; rr < 4; rr++) {
                o[rr][0] += pv[rr].x * vv[0].x; o[rr][1] += pv[rr].x * vv[0].y;
                o[rr][0] += pv[rr].y * vv[1].x; o[rr][1] += pv[rr].y * vv[1].y;
                o[rr][0] += pv[rr].z * vv[2].x; o[rr][1] += pv[rr].z * vv[2].y;
                o[rr][0] += pv[rr].w * vv[3].x; o[rr][1] += pv[rr].w * vv[3].y;
            }
        }
    }

    int base = (zsp * NH + h) * R + q0;
    #pragma unroll
    for (int rr = 0; rr < 4; rr++) {
        g_po[(size_t)(base + 4 * tr + rr) * CHID + 2 * tc + 0] = o[rr][0];
        g_po[(size_t)(base + 4 * tr + rr) * CHID + 2 * tc + 1] = o[rr][1];
    }
    __syncthreads();
    if (tid < 64) {
        g_pm[base + tid] = m_s[tid];
        g_pl[base + tid] = l_s[tid];
    }
}

// ---------------------------------------------------------------------------
// K4b: merge split-j partials -> g_o
// ---------------------------------------------------------------------------
__global__ void k_merge() {
    int idx = blockIdx.x * 256 + threadIdx.x;      // over NH*R*CHID = 262144
    int d = idx & (CHID - 1);
    int q = (idx >> 5) & (R - 1);
    int h = idx >> 15;

    float mv[NSPLIT];
    float M = -1e30f;
    #pragma unroll
    for (int s2 = 0; s2 < NSPLIT; s2++) {
        mv[s2] = g_pm[(s2 * NH + h) * R + q];
        M = fmaxf(M, mv[s2]);
    }
    float L = 0.f, ov = 0.f;
    #pragma unroll
    for (int s2 = 0; s2 < NSPLIT; s2++) {
        float e = __expf(mv[s2] - M);
        L  += g_pl[(s2 * NH + h) * R + q] * e;
        ov += g_po[(size_t)((s2 * NH + h) * R + q) * CHID + d] * e;
    }
    g_o[q * HD + h * CHID + d] = ov / L;
}

// ---------------------------------------------------------------------------
// K5: out = (o * sigmoid(gw)) @ Wo + bo
// ---------------------------------------------------------------------------
__global__ void k_out(const float* __restrict__ Wo,
                      const float* __restrict__ bo,
                      float* __restrict__ out) {
    int r0 = blockIdx.y * 64, c0 = blockIdx.x * 64;
    __shared__ float As[32][72];
    __shared__ float Bs[32][72];
    int tid = threadIdx.x;
    int tr = tid >> 4, tc = tid & 15;
    float acc[4][4] = {};

    for (int k0 = 0; k0 < HD; k0 += 32) {
        #pragma unroll
        for (int t = 0; t < 8; t++) {
            int idx = tid + t * 256;
            int r = idx >> 5, kk = idx & 31;
            int gi = (r0 + r) * HD + k0 + kk;
            float gate = 1.0f / (1.0f + __expf(-g_gw[gi]));
            As[kk][r] = g_o[gi] * gate;
        }
        #pragma unroll
        for (int t = 0; t < 8; t++) {
            int idx = tid + t * 256;
            int kk = idx >> 6, cc = idx & 63;
            Bs[kk][cc] = Wo[(k0 + kk) * CIN + c0 + cc];
        }
        __syncthreads();
        #pragma unroll
        for (int kk = 0; kk < 32; kk++) {
            float4 a4 = *(const float4*)&As[kk][4 * tr];
            float4 b4 = *(const float4*)&Bs[kk][4 * tc];
            float av[4] = {a4.x, a4.y, a4.z, a4.w};
            float bv[4] = {b4.x, b4.y, b4.z, b4.w};
            #pragma unroll
            for (int rr = 0; rr < 4; rr++)
                #pragma unroll
                for (int cc = 0; cc < 4; cc++)
                    acc[rr][cc] += av[rr] * bv[cc];
        }
        __syncthreads();
    }
    #pragma unroll
    for (int rr = 0; rr < 4; rr++) {
        int c = c0 + 4 * tc;
        float4 o4 = make_float4(acc[rr][0] + bo[c + 0], acc[rr][1] + bo[c + 1],
                                acc[rr][2] + bo[c + 2], acc[rr][3] + bo[c + 3]);
        *(float4*)&out[(r0 + 4 * tr + rr) * CIN + c] = o4;
    }
}

// ---------------------------------------------------------------------------
extern "C" void kernel_launch(void* const* d_in, const int* in_sizes, int n_in,
                              void* d_out, int out_size) {
    const float* m      = (const float*)d_in[0];
    const float* z      = (const float*)d_in[1];
    const float* ln_m_w = (const float*)d_in[2];
    const float* ln_m_b = (const float*)d_in[3];
    const float* ln_z_w = (const float*)d_in[4];
    const float* ln_z_b = (const float*)d_in[5];
    const float* Wz     = (const float*)d_in[6];
    const float* Wq     = (const float*)d_in[7];
    const float* Wk     = (const float*)d_in[8];
    const float* Wv     = (const float*)d_in[9];
    const float* Wg     = (const float*)d_in[10];
    // d_in[11] = bg (unused by reference)
    const float* Wo     = (const float*)d_in[12];
    const float* bo     = (const float*)d_in[13];
    float* out = (float*)d_out;

    k_lnm<<<R, 256>>>(m, ln_m_w, ln_m_b);
    k_qkvg<<<dim3(4, 16, 4), 256>>>(Wq, Wk, Wv, Wg);
    k_bias<<<dim3(8, R), 128>>>(z, ln_z_w, ln_z_b, Wz);
    k_attn<<<dim3(16, NH, NSPLIT), 256>>>();
    k_merge<<<NH * R * CHID / 256, 256>>>();
    k_out<<<dim3(4, 16), 256>>>(Wo, bo, out);
}

// round 11
// speedup vs baseline: 1.3084x; 1.1395x over previous
#include <cuda_runtime.h>
#include <math.h>
#include <stdint.h>

#define R 1024
#define CIN 256
#define CHID 32
#define NH 8
#define CZ 128
#define HD 256   // NH*CHID
#define NSPLIT 8

// Scratch (static device globals — no runtime allocation)
__device__ float g_mn[R * CIN];
__device__ float g_q[R * HD];
__device__ float g_k[R * HD];
__device__ float g_v[R * HD];
__device__ float g_gw[R * HD];
__device__ float g_bias[(size_t)NH * R * R];   // 32 MB, layout [h][i][j]
__device__ float g_o[R * HD];
__device__ float g_pm[NSPLIT * NH * R];
__device__ float g_pl[NSPLIT * NH * R];
__device__ float g_po[(size_t)NSPLIT * NH * R * CHID];
__device__ unsigned long long g_wq[64 * NH];   // packed bias weights
__device__ float g_cs[NH], g_cb[NH];

// ---- packed f32x2 helpers (FFMA2 — only reachable via PTX) ----------------
__device__ __forceinline__ unsigned long long fma2(unsigned long long a,
                                                   unsigned long long b,
                                                   unsigned long long c) {
    unsigned long long d;
    asm("fma.rn.f32x2 %0, %1, %2, %3;" : "=l"(d) : "l"(a), "l"(b), "l"(c));
    return d;
}
__device__ __forceinline__ unsigned long long add2(unsigned long long a,
                                                   unsigned long long b) {
    unsigned long long d;
    asm("add.rn.f32x2 %0, %1, %2;" : "=l"(d) : "l"(a), "l"(b));
    return d;
}
__device__ __forceinline__ float2 unpk2(unsigned long long v) {
    float2 r;
    asm("mov.b64 {%0, %1}, %2;" : "=f"(r.x), "=f"(r.y) : "l"(v));
    return r;
}
__device__ __forceinline__ unsigned long long pk2(float a, float b) {
    unsigned long long d;
    asm("mov.b64 %0, {%1, %2};" : "=l"(d) : "f"(a), "f"(b));
    return d;
}
__device__ __forceinline__ void cpa16(uint32_t dst, const void* src) {
    asm volatile("cp.async.cg.shared.global [%0], [%1], 16;" :: "r"(dst), "l"(src));
}
__device__ __forceinline__ void cpa_commit() {
    asm volatile("cp.async.commit_group;" ::: "memory");
}
template <int N>
__device__ __forceinline__ void cpa_wait() {
    asm volatile("cp.async.wait_group %0;" :: "n"(N) : "memory");
}

// ---------------------------------------------------------------------------
// K0: one-block prep — packed bias weight table + per-head colsum/cbias
// ---------------------------------------------------------------------------
__global__ void k_prep(const float* __restrict__ lnw,
                       const float* __restrict__ lnb,
                       const float* __restrict__ Wz) {
    int tid = threadIdx.x;   // 64 threads
    float l0 = lnw[2 * tid], l1 = lnw[2 * tid + 1];
    #pragma unroll
    for (int h = 0; h < NH; h++)
        g_wq[tid * NH + h] =
            pk2(l0 * Wz[(2 * tid) * NH + h], l1 * Wz[(2 * tid + 1) * NH + h]);
    if (tid < NH) {
        float cs = 0.f, cb = 0.f;
        #pragma unroll 4
        for (int c = 0; c < CZ; c++) {
            float wv = Wz[c * NH + tid];
            cs += lnw[c] * wv;
            cb += lnb[c] * wv;
        }
        g_cs[tid] = cs;
        g_cb[tid] = cb;
    }
}

// ---------------------------------------------------------------------------
// K1: mn = LayerNorm(m) * w + b
// ---------------------------------------------------------------------------
__global__ void k_lnm(const float* __restrict__ m,
                      const float* __restrict__ w,
                      const float* __restrict__ b) {
    int row = blockIdx.x;
    int c = threadIdx.x;
    float x = m[row * CIN + c];
    float s = x, ss = x * x;
    __shared__ float red[16];
    #pragma unroll
    for (int o = 16; o > 0; o >>= 1) {
        s  += __shfl_xor_sync(0xffffffffu, s, o);
        ss += __shfl_xor_sync(0xffffffffu, ss, o);
    }
    int lane = c & 31, wid = c >> 5;
    if (lane == 0) { red[wid] = s; red[wid + 8] = ss; }
    __syncthreads();
    if (c == 0) {
        float s2 = 0.f, ss2 = 0.f;
        #pragma unroll
        for (int i = 0; i < 8; i++) { s2 += red[i]; ss2 += red[i + 8]; }
        red[0] = s2; red[8] = ss2;
    }
    __syncthreads();
    float mu  = red[0] * (1.0f / CIN);
    float var = red[8] * (1.0f / CIN) - mu * mu;
    float rs  = rsqrtf(var + 1e-5f);
    g_mn[row * CIN + c] = (x - mu) * rs * w[c] + b[c];
}

// ---------------------------------------------------------------------------
// K2: Q,K,V,Gw = mn @ {Wq,Wk,Wv,Wg}
// ---------------------------------------------------------------------------
__global__ void k_qkvg(const float* __restrict__ Wq, const float* __restrict__ Wk,
                       const float* __restrict__ Wv, const float* __restrict__ Wg) {
    const float* W;
    float* out;
    float scale = 1.0f;
    int mz = blockIdx.z;
    if (mz == 0)      { W = Wq; out = g_q; scale = 0.17677669529663687f; }
    else if (mz == 1) { W = Wk; out = g_k; }
    else if (mz == 2) { W = Wv; out = g_v; }
    else              { W = Wg; out = g_gw; }

    int r0 = blockIdx.y * 64, c0 = blockIdx.x * 64;
    __shared__ float As[32][72];
    __shared__ float Bs[32][72];
    int tid = threadIdx.x;
    int tr = tid >> 4, tc = tid & 15;
    float acc[4][4] = {};

    for (int k0 = 0; k0 < CIN; k0 += 32) {
        #pragma unroll
        for (int t = 0; t < 8; t++) {
            int idx = tid + t * 256;
            int r = idx >> 5, kk = idx & 31;
            As[kk][r] = g_mn[(r0 + r) * CIN + k0 + kk];
        }
        #pragma unroll
        for (int t = 0; t < 8; t++) {
            int idx = tid + t * 256;
            int kk = idx >> 6, cc = idx & 63;
            Bs[kk][cc] = W[(k0 + kk) * HD + c0 + cc];
        }
        __syncthreads();
        #pragma unroll
        for (int kk = 0; kk < 32; kk++) {
            float4 a4 = *(const float4*)&As[kk][4 * tr];
            float4 b4 = *(const float4*)&Bs[kk][4 * tc];
            float av[4] = {a4.x, a4.y, a4.z, a4.w};
            float bv[4] = {b4.x, b4.y, b4.z, b4.w};
            #pragma unroll
            for (int rr = 0; rr < 4; rr++)
                #pragma unroll
                for (int cc = 0; cc < 4; cc++)
                    acc[rr][cc] += av[rr] * bv[cc];
        }
        __syncthreads();
    }
    #pragma unroll
    for (int rr = 0; rr < 4; rr++) {
        float4 o4 = make_float4(acc[rr][0] * scale, acc[rr][1] * scale,
                                acc[rr][2] * scale, acc[rr][3] * scale);
        *(float4*)&out[(r0 + 4 * tr + rr) * HD + c0 + 4 * tc] = o4;
    }
}

// ---------------------------------------------------------------------------
// K3 (v10 = round-7 k_bias with hoisted prologue): thread-per-row, 64 thr,
// cp.async single buffer, 4x64-row tiles, grid (4, 1024).
// Prologue replaced by cheap coalesced copies from g_wq/g_cs/g_cb; tile-0
// cp.async issued FIRST so DRAM starts before the table copy.
// ---------------------------------------------------------------------------
#define BT_ROWS 64
#define BT_STRIDE 132     // words per row in smem
#define BT_TILES 4

__global__ __launch_bounds__(64) void k_bias(const float* __restrict__ z) {
    __shared__ __align__(16) float zs[BT_ROWS * BT_STRIDE];
    __shared__ __align__(16) unsigned long long wq[64 * NH];
    __shared__ float s_cs[NH], s_cb[NH];

    int tid = threadIdx.x;
    int i  = blockIdx.y;
    int jb = blockIdx.x * (BT_ROWS * BT_TILES);   // 256-j strip

    const float* zstrip = z + ((size_t)i * R + jb) * CZ;
    uint32_t zs_base = (uint32_t)__cvta_generic_to_shared(&zs[0]);

    // ---- issue tile 0 immediately (32 x 16B per thread)
    #pragma unroll
    for (int k = 0; k < 32; k++) {
        int idx = tid + k * 64;            // 0..2047 float4 slots
        int row = idx >> 5, s4 = idx & 31;
        uint32_t dw = (uint32_t)(row * BT_STRIDE + s4 * 4 + ((s4 >= 16) ? 4 : 0));
        cpa16(zs_base + dw * 4, zstrip + row * CZ + s4 * 4);
    }
    cpa_commit();

    // ---- cheap table copy (overlaps the tile-0 fetch)
    {
        ulonglong2* wq2 = (ulonglong2*)wq;
        const ulonglong2* gw2 = (const ulonglong2*)g_wq;
        #pragma unroll
        for (int k2 = 0; k2 < 4; k2++)
            wq2[tid + k2 * 64] = gw2[tid + k2 * 64];
        if (tid < NH) { s_cs[tid] = g_cs[tid]; s_cb[tid] = g_cb[tid]; }
    }

    // ---- main loop over 4 tiles, single buffer (inter-block overlap)
    for (int tt = 0; tt < BT_TILES; tt++) {
        cpa_wait<0>();
        __syncthreads();   // tile ready + (first iter) wq/s_cs/s_cb visible

        // ---- compute: thread tid owns row tid of this tile
        const float* zr = &zs[tid * BT_STRIDE];
        unsigned long long aD[NH] = {0ull,0ull,0ull,0ull,0ull,0ull,0ull,0ull};
        unsigned long long aS = 0ull, aQ = 0ull;

        #pragma unroll
        for (int half = 0; half < 2; half++) {
            const float* zh = zr + half * 68;          // padded half offset
            #pragma unroll
            for (int u = 0; u < 16; u++) {
                ulonglong2 zz = *(const ulonglong2*)(zh + 4 * u);
                aS = add2(aS, add2(zz.x, zz.y));
                aQ = fma2(zz.x, zz.x, aQ);
                aQ = fma2(zz.y, zz.y, aQ);
                int p = half * 32 + 2 * u;
                const ulonglong2* w0 = (const ulonglong2*)&wq[p * NH];
                const ulonglong2* w1 = (const ulonglong2*)&wq[(p + 1) * NH];
                #pragma unroll
                for (int q2 = 0; q2 < 4; q2++) {
                    ulonglong2 wa = w0[q2];
                    ulonglong2 wb = w1[q2];
                    aD[2 * q2]     = fma2(zz.x, wa.x, aD[2 * q2]);
                    aD[2 * q2 + 1] = fma2(zz.x, wa.y, aD[2 * q2 + 1]);
                    aD[2 * q2]     = fma2(zz.y, wb.x, aD[2 * q2]);
                    aD[2 * q2 + 1] = fma2(zz.y, wb.y, aD[2 * q2 + 1]);
                }
            }
        }

        float2 dS = unpk2(aS), dQ = unpk2(aQ);
        float s  = dS.x + dS.y;
        float qq = dQ.x + dQ.y;
        float mu  = s * (1.0f / CZ);
        float var = qq * (1.0f / CZ) - mu * mu;
        float rs  = rsqrtf(var + 1e-5f);

        size_t j = (size_t)(jb + tt * BT_ROWS + tid);
        #pragma unroll
        for (int h = 0; h < NH; h++) {
            float2 dd = unpk2(aD[h]);
            float dot = dd.x + dd.y;
            float bv = rs * (dot - mu * s_cs[h]) + s_cb[h];
            g_bias[((size_t)h * R + i) * R + j] = bv;
        }
        __syncthreads();   // zs safe for reuse by next tile's loads

        if (tt + 1 < BT_TILES) {
            const float* src = zstrip + (size_t)(tt + 1) * BT_ROWS * CZ;
            #pragma unroll
            for (int k = 0; k < 32; k++) {
                int idx = tid + k * 64;
                int row = idx >> 5, s4 = idx & 31;
                uint32_t dw = (uint32_t)(row * BT_STRIDE + s4 * 4 + ((s4 >= 16) ? 4 : 0));
                cpa16(zs_base + dw * 4, src + row * CZ + s4 * 4);
            }
            cpa_commit();
        }
    }
}

// ---------------------------------------------------------------------------
// K4: flash attention with additive bias, SPLIT over j (NSPLIT=8).
// grid (16 q-tiles, 8 heads, 8 j-splits), 256 threads; 128 j per block.
// ---------------------------------------------------------------------------
__global__ void k_attn() {
    int h   = blockIdx.y;
    int q0  = blockIdx.x * 64;
    int zsp = blockIdx.z;
    int tid = threadIdx.x;
    int tr = tid >> 4, tc = tid & 15;

    __shared__ float qT[32][72];
    __shared__ float kT[32][72];
    __shared__ float vs[64][36];
    __shared__ float ps[64][68];
    __shared__ float m_s[64], l_s[64], f_s[64];

    #pragma unroll
    for (int t = 0; t < 8; t++) {
        int idx = tid + t * 256;
        int r = idx >> 5, d = idx & 31;
        qT[d][r] = g_q[(q0 + r) * HD + h * CHID + d];
    }
    if (tid < 64) { m_s[tid] = -1e30f; l_s[tid] = 0.f; }

    float o[4][2] = {};

    for (int jt = 0; jt < 2; jt++) {
        int j0 = zsp * 128 + jt * 64;
        __syncthreads();
        #pragma unroll
        for (int t = 0; t < 8; t++) {
            int idx = tid + t * 256;
            int r = idx >> 5, d = idx & 31;
            kT[d][r] = g_k[(j0 + r) * HD + h * CHID + d];
            vs[r][d] = g_v[(j0 + r) * HD + h * CHID + d];
        }
        __syncthreads();

        float s[4][4];
        #pragma unroll
        for (int rr = 0; rr < 4; rr++) {
            float4 b4 = *(const float4*)&g_bias[((size_t)h * R + q0 + 4 * tr + rr) * R + j0 + 4 * tc];
            s[rr][0] = b4.x; s[rr][1] = b4.y; s[rr][2] = b4.z; s[rr][3] = b4.w;
        }
        #pragma unroll
        for (int kk = 0; kk < 32; kk++) {
            float4 a4 = *(const float4*)&qT[kk][4 * tr];
            float4 b4 = *(const float4*)&kT[kk][4 * tc];
            float av[4] = {a4.x, a4.y, a4.z, a4.w};
            float bv[4] = {b4.x, b4.y, b4.z, b4.w};
            #pragma unroll
            for (int rr = 0; rr < 4; rr++)
                #pragma unroll
                for (int cc = 0; cc < 4; cc++)
                    s[rr][cc] += av[rr] * bv[cc];
        }
        #pragma unroll
        for (int rr = 0; rr < 4; rr++)
            *(float4*)&ps[4 * tr + rr][4 * tc] =
                make_float4(s[rr][0], s[rr][1], s[rr][2], s[rr][3]);
        __syncthreads();

        {
            int row = tid >> 2, p = tid & 3;
            float mo = m_s[row];
            float mc = -1e30f;
            #pragma unroll
            for (int c = 0; c < 16; c += 4) {
                float4 v = *(const float4*)&ps[row][p * 16 + c];
                mc = fmaxf(mc, fmaxf(fmaxf(v.x, v.y), fmaxf(v.z, v.w)));
            }
            mc = fmaxf(mc, __shfl_xor_sync(0xffffffffu, mc, 1));
            mc = fmaxf(mc, __shfl_xor_sync(0xffffffffu, mc, 2));
            float mn2 = fmaxf(mo, mc);
            float l = 0.f;
            #pragma unroll
            for (int c = 0; c < 16; c += 4) {
                float4 v = *(const float4*)&ps[row][p * 16 + c];
                v.x = __expf(v.x - mn2); v.y = __expf(v.y - mn2);
                v.z = __expf(v.z - mn2); v.w = __expf(v.w - mn2);
                *(float4*)&ps[row][p * 16 + c] = v;
                l += v.x + v.y + v.z + v.w;
            }
            l += __shfl_xor_sync(0xffffffffu, l, 1);
            l += __shfl_xor_sync(0xffffffffu, l, 2);
            if (p == 0) {
                float f = __expf(mo - mn2);
                f_s[row] = f;
                l_s[row] = l_s[row] * f + l;
                m_s[row] = mn2;
            }
        }
        __syncthreads();

        float fr[4];
        #pragma unroll
        for (int rr = 0; rr < 4; rr++) fr[rr] = f_s[4 * tr + rr];
        #pragma unroll
        for (int rr = 0; rr < 4; rr++) { o[rr][0] *= fr[rr]; o[rr][1] *= fr[rr]; }

        #pragma unroll
        for (int j = 0; j < 64; j += 4) {
            float4 pv[4];
            #pragma unroll
            for (int rr = 0; rr < 4; rr++)
                pv[rr] = *(const float4*)&ps[4 * tr + rr][j];
            float2 vv[4];
            #pragma unroll
            for (int e = 0; e < 4; e++)
                vv[e] = *(const float2*)&vs[j + e][2 * tc];
            #pragma unroll
            for (int rr = 0; rr < 4; rr++) {
                o[rr][0] += pv[rr].x * vv[0].x; o[rr][1] += pv[rr].x * vv[0].y;
                o[rr][0] += pv[rr].y * vv[1].x; o[rr][1] += pv[rr].y * vv[1].y;
                o[rr][0] += pv[rr].z * vv[2].x; o[rr][1] += pv[rr].z * vv[2].y;
                o[rr][0] += pv[rr].w * vv[3].x; o[rr][1] += pv[rr].w * vv[3].y;
            }
        }
    }

    int base = (zsp * NH + h) * R + q0;
    #pragma unroll
    for (int rr = 0; rr < 4; rr++) {
        g_po[(size_t)(base + 4 * tr + rr) * CHID + 2 * tc + 0] = o[rr][0];
        g_po[(size_t)(base + 4 * tr + rr) * CHID + 2 * tc + 1] = o[rr][1];
    }
    __syncthreads();
    if (tid < 64) {
        g_pm[base + tid] = m_s[tid];
        g_pl[base + tid] = l_s[tid];
    }
}

// ---------------------------------------------------------------------------
// K4b: merge split-j partials -> g_o
// ---------------------------------------------------------------------------
__global__ void k_merge() {
    int idx = blockIdx.x * 256 + threadIdx.x;      // over NH*R*CHID = 262144
    int d = idx & (CHID - 1);
    int q = (idx >> 5) & (R - 1);
    int h = idx >> 15;

    float mv[NSPLIT];
    float M = -1e30f;
    #pragma unroll
    for (int s2 = 0; s2 < NSPLIT; s2++) {
        mv[s2] = g_pm[(s2 * NH + h) * R + q];
        M = fmaxf(M, mv[s2]);
    }
    float L = 0.f, ov = 0.f;
    #pragma unroll
    for (int s2 = 0; s2 < NSPLIT; s2++) {
        float e = __expf(mv[s2] - M);
        L  += g_pl[(s2 * NH + h) * R + q] * e;
        ov += g_po[(size_t)((s2 * NH + h) * R + q) * CHID + d] * e;
    }
    g_o[q * HD + h * CHID + d] = ov / L;
}

// ---------------------------------------------------------------------------
// K5: out = (o * sigmoid(gw)) @ Wo + bo
// ---------------------------------------------------------------------------
__global__ void k_out(const float* __restrict__ Wo,
                      const float* __restrict__ bo,
                      float* __restrict__ out) {
    int r0 = blockIdx.y * 64, c0 = blockIdx.x * 64;
    __shared__ float As[32][72];
    __shared__ float Bs[32][72];
    int tid = threadIdx.x;
    int tr = tid >> 4, tc = tid & 15;
    float acc[4][4] = {};

    for (int k0 = 0; k0 < HD; k0 += 32) {
        #pragma unroll
        for (int t = 0; t < 8; t++) {
            int idx = tid + t * 256;
            int r = idx >> 5, kk = idx & 31;
            int gi = (r0 + r) * HD + k0 + kk;
            float gate = 1.0f / (1.0f + __expf(-g_gw[gi]));
            As[kk][r] = g_o[gi] * gate;
        }
        #pragma unroll
        for (int t = 0; t < 8; t++) {
            int idx = tid + t * 256;
            int kk = idx >> 6, cc = idx & 63;
            Bs[kk][cc] = Wo[(k0 + kk) * CIN + c0 + cc];
        }
        __syncthreads();
        #pragma unroll
        for (int kk = 0; kk < 32; kk++) {
            float4 a4 = *(const float4*)&As[kk][4 * tr];
            float4 b4 = *(const float4*)&Bs[kk][4 * tc];
            float av[4] = {a4.x, a4.y, a4.z, a4.w};
            float bv[4] = {b4.x, b4.y, b4.z, b4.w};
            #pragma unroll
            for (int rr = 0; rr < 4; rr++)
                #pragma unroll
                for (int cc = 0; cc < 4; cc++)
                    acc[rr][cc] += av[rr] * bv[cc];
        }
        __syncthreads();
    }
    #pragma unroll
    for (int rr = 0; rr < 4; rr++) {
        int c = c0 + 4 * tc;
        float4 o4 = make_float4(acc[rr][0] + bo[c + 0], acc[rr][1] + bo[c + 1],
                                acc[rr][2] + bo[c + 2], acc[rr][3] + bo[c + 3]);
        *(float4*)&out[(r0 + 4 * tr + rr) * CIN + c] = o4;
    }
}

// ---------------------------------------------------------------------------
extern "C" void kernel_launch(void* const* d_in, const int* in_sizes, int n_in,
                              void* d_out, int out_size) {
    const float* m      = (const float*)d_in[0];
    const float* z      = (const float*)d_in[1];
    const float* ln_m_w = (const float*)d_in[2];
    const float* ln_m_b = (const float*)d_in[3];
    const float* ln_z_w = (const float*)d_in[4];
    const float* ln_z_b = (const float*)d_in[5];
    const float* Wz     = (const float*)d_in[6];
    const float* Wq     = (const float*)d_in[7];
    const float* Wk     = (const float*)d_in[8];
    const float* Wv     = (const float*)d_in[9];
    const float* Wg     = (const float*)d_in[10];
    // d_in[11] = bg (unused by reference)
    const float* Wo     = (const float*)d_in[12];
    const float* bo     = (const float*)d_in[13];
    float* out = (float*)d_out;

    k_prep<<<1, 64>>>(ln_z_w, ln_z_b, Wz);
    k_lnm<<<R, 256>>>(m, ln_m_w, ln_m_b);
    k_qkvg<<<dim3(4, 16, 4), 256>>>(Wq, Wk, Wv, Wg);
    k_bias<<<dim3(4, R), 64>>>(z);
    k_attn<<<dim3(16, NH, NSPLIT), 256>>>();
    k_merge<<<NH * R * CHID / 256, 256>>>();
    k_out<<<dim3(4, 16), 256>>>(Wo, bo, out);
}

// round 12
// speedup vs baseline: 1.3829x; 1.0569x over previous
#include <cuda_runtime.h>
#include <math.h>
#include <stdint.h>

#define R 1024
#define CIN 256
#define CHID 32
#define NH 8
#define CZ 128
#define HD 256   // NH*CHID
#define NSPLIT 8

// Scratch (static device globals — no runtime allocation)
__device__ float g_mn[R * CIN];
__device__ float g_q[R * HD];
__device__ float g_k[R * HD];
__device__ float g_v[R * HD];
__device__ float g_gw[R * HD];
__device__ float g_bias[(size_t)NH * R * R];   // 32 MB, layout [h][i][j]
__device__ float g_o[R * HD];
__device__ float g_pm[NSPLIT * NH * R];
__device__ float g_pl[NSPLIT * NH * R];
__device__ float g_po[(size_t)NSPLIT * NH * R * CHID];
__device__ unsigned long long g_wq[64 * NH];   // packed bias weights
__device__ float g_cs[NH], g_cb[NH];

// ---- packed f32x2 helpers (FFMA2 — only reachable via PTX) ----------------
__device__ __forceinline__ unsigned long long fma2(unsigned long long a,
                                                   unsigned long long b,
                                                   unsigned long long c) {
    unsigned long long d;
    asm("fma.rn.f32x2 %0, %1, %2, %3;" : "=l"(d) : "l"(a), "l"(b), "l"(c));
    return d;
}
__device__ __forceinline__ unsigned long long add2(unsigned long long a,
                                                   unsigned long long b) {
    unsigned long long d;
    asm("add.rn.f32x2 %0, %1, %2;" : "=l"(d) : "l"(a), "l"(b));
    return d;
}
__device__ __forceinline__ float2 unpk2(unsigned long long v) {
    float2 r;
    asm("mov.b64 {%0, %1}, %2;" : "=f"(r.x), "=f"(r.y) : "l"(v));
    return r;
}
__device__ __forceinline__ unsigned long long pk2(float a, float b) {
    unsigned long long d;
    asm("mov.b64 %0, {%1, %2};" : "=l"(d) : "f"(a), "f"(b));
    return d;
}
__device__ __forceinline__ void cpa16(uint32_t dst, const void* src) {
    asm volatile("cp.async.cg.shared.global [%0], [%1], 16;" :: "r"(dst), "l"(src));
}
__device__ __forceinline__ void cpa_commit() {
    asm volatile("cp.async.commit_group;" ::: "memory");
}
template <int N>
__device__ __forceinline__ void cpa_wait() {
    asm volatile("cp.async.wait_group %0;" :: "n"(N) : "memory");
}

// ---------------------------------------------------------------------------
// K0: one-block prep — packed bias weight table + per-head colsum/cbias.
// 256 threads: wq by threads 0-63 (8 parallel LDG each); cs/cb by threads
// 128-255 (16 per head, 8 c-values each) + smem reduction. ~2us.
// ---------------------------------------------------------------------------
__global__ void k_prep(const float* __restrict__ lnw,
                       const float* __restrict__ lnb,
                       const float* __restrict__ Wz) {
    __shared__ float red_cs[NH][17], red_cb[NH][17];
    int tid = threadIdx.x;   // 256
    if (tid < 64) {
        float l0 = lnw[2 * tid], l1 = lnw[2 * tid + 1];
        #pragma unroll
        for (int h = 0; h < NH; h++)
            g_wq[tid * NH + h] =
                pk2(l0 * Wz[(2 * tid) * NH + h], l1 * Wz[(2 * tid + 1) * NH + h]);
    }
    if (tid >= 128) {
        int t = tid - 128;          // 0..127
        int h = t >> 4, l16 = t & 15;
        float cs = 0.f, cb = 0.f;
        #pragma unroll
        for (int k = 0; k < 8; k++) {
            int c = l16 + 16 * k;
            float wv = Wz[c * NH + h];
            cs += lnw[c] * wv;
            cb += lnb[c] * wv;
        }
        red_cs[h][l16] = cs;
        red_cb[h][l16] = cb;
    }
    __syncthreads();
    if (tid < NH) {
        float cs = 0.f, cb = 0.f;
        #pragma unroll
        for (int k = 0; k < 16; k++) { cs += red_cs[tid][k]; cb += red_cb[tid][k]; }
        g_cs[tid] = cs;
        g_cb[tid] = cb;
    }
}

// ---------------------------------------------------------------------------
// K1: mn = LayerNorm(m) * w + b
// ---------------------------------------------------------------------------
__global__ void k_lnm(const float* __restrict__ m,
                      const float* __restrict__ w,
                      const float* __restrict__ b) {
    int row = blockIdx.x;
    int c = threadIdx.x;
    float x = m[row * CIN + c];
    float s = x, ss = x * x;
    __shared__ float red[16];
    #pragma unroll
    for (int o = 16; o > 0; o >>= 1) {
        s  += __shfl_xor_sync(0xffffffffu, s, o);
        ss += __shfl_xor_sync(0xffffffffu, ss, o);
    }
    int lane = c & 31, wid = c >> 5;
    if (lane == 0) { red[wid] = s; red[wid + 8] = ss; }
    __syncthreads();
    if (c == 0) {
        float s2 = 0.f, ss2 = 0.f;
        #pragma unroll
        for (int i = 0; i < 8; i++) { s2 += red[i]; ss2 += red[i + 8]; }
        red[0] = s2; red[8] = ss2;
    }
    __syncthreads();
    float mu  = red[0] * (1.0f / CIN);
    float var = red[8] * (1.0f / CIN) - mu * mu;
    float rs  = rsqrtf(var + 1e-5f);
    g_mn[row * CIN + c] = (x - mu) * rs * w[c] + b[c];
}

// ---------------------------------------------------------------------------
// K2: Q,K,V,Gw = mn @ {Wq,Wk,Wv,Wg}
// ---------------------------------------------------------------------------
__global__ void k_qkvg(const float* __restrict__ Wq, const float* __restrict__ Wk,
                       const float* __restrict__ Wv, const float* __restrict__ Wg) {
    const float* W;
    float* out;
    float scale = 1.0f;
    int mz = blockIdx.z;
    if (mz == 0)      { W = Wq; out = g_q; scale = 0.17677669529663687f; }
    else if (mz == 1) { W = Wk; out = g_k; }
    else if (mz == 2) { W = Wv; out = g_v; }
    else              { W = Wg; out = g_gw; }

    int r0 = blockIdx.y * 64, c0 = blockIdx.x * 64;
    __shared__ float As[32][72];
    __shared__ float Bs[32][72];
    int tid = threadIdx.x;
    int tr = tid >> 4, tc = tid & 15;
    float acc[4][4] = {};

    for (int k0 = 0; k0 < CIN; k0 += 32) {
        #pragma unroll
        for (int t = 0; t < 8; t++) {
            int idx = tid + t * 256;
            int r = idx >> 5, kk = idx & 31;
            As[kk][r] = g_mn[(r0 + r) * CIN + k0 + kk];
        }
        #pragma unroll
        for (int t = 0; t < 8; t++) {
            int idx = tid + t * 256;
            int kk = idx >> 6, cc = idx & 63;
            Bs[kk][cc] = W[(k0 + kk) * HD + c0 + cc];
        }
        __syncthreads();
        #pragma unroll
        for (int kk = 0; kk < 32; kk++) {
            float4 a4 = *(const float4*)&As[kk][4 * tr];
            float4 b4 = *(const float4*)&Bs[kk][4 * tc];
            float av[4] = {a4.x, a4.y, a4.z, a4.w};
            float bv[4] = {b4.x, b4.y, b4.z, b4.w};
            #pragma unroll
            for (int rr = 0; rr < 4; rr++)
                #pragma unroll
                for (int cc = 0; cc < 4; cc++)
                    acc[rr][cc] += av[rr] * bv[cc];
        }
        __syncthreads();
    }
    #pragma unroll
    for (int rr = 0; rr < 4; rr++) {
        float4 o4 = make_float4(acc[rr][0] * scale, acc[rr][1] * scale,
                                acc[rr][2] * scale, acc[rr][3] * scale);
        *(float4*)&out[(r0 + 4 * tr + rr) * HD + c0 + 4 * tc] = o4;
    }
}

// ---------------------------------------------------------------------------
// K3 (round-11 proven): thread-per-row, 64 thr, cp.async single buffer,
// 4x64-row tiles, grid (4, 1024). Prologue hoisted to k_prep.
// ---------------------------------------------------------------------------
#define BT_ROWS 64
#define BT_STRIDE 132     // words per row in smem
#define BT_TILES 4

__global__ __launch_bounds__(64) void k_bias(const float* __restrict__ z) {
    __shared__ __align__(16) float zs[BT_ROWS * BT_STRIDE];
    __shared__ __align__(16) unsigned long long wq[64 * NH];
    __shared__ float s_cs[NH], s_cb[NH];

    int tid = threadIdx.x;
    int i  = blockIdx.y;
    int jb = blockIdx.x * (BT_ROWS * BT_TILES);   // 256-j strip

    const float* zstrip = z + ((size_t)i * R + jb) * CZ;
    uint32_t zs_base = (uint32_t)__cvta_generic_to_shared(&zs[0]);

    // ---- issue tile 0 immediately (32 x 16B per thread)
    #pragma unroll
    for (int k = 0; k < 32; k++) {
        int idx = tid + k * 64;            // 0..2047 float4 slots
        int row = idx >> 5, s4 = idx & 31;
        uint32_t dw = (uint32_t)(row * BT_STRIDE + s4 * 4 + ((s4 >= 16) ? 4 : 0));
        cpa16(zs_base + dw * 4, zstrip + row * CZ + s4 * 4);
    }
    cpa_commit();

    // ---- cheap table copy (overlaps the tile-0 fetch)
    {
        ulonglong2* wq2 = (ulonglong2*)wq;
        const ulonglong2* gw2 = (const ulonglong2*)g_wq;
        #pragma unroll
        for (int k2 = 0; k2 < 4; k2++)
            wq2[tid + k2 * 64] = gw2[tid + k2 * 64];
        if (tid < NH) { s_cs[tid] = g_cs[tid]; s_cb[tid] = g_cb[tid]; }
    }

    // ---- main loop over 4 tiles, single buffer (inter-block overlap)
    for (int tt = 0; tt < BT_TILES; tt++) {
        cpa_wait<0>();
        __syncthreads();   // tile ready + (first iter) wq/s_cs/s_cb visible

        // ---- compute: thread tid owns row tid of this tile
        const float* zr = &zs[tid * BT_STRIDE];
        unsigned long long aD[NH] = {0ull,0ull,0ull,0ull,0ull,0ull,0ull,0ull};
        unsigned long long aS = 0ull, aQ = 0ull;

        #pragma unroll
        for (int half = 0; half < 2; half++) {
            const float* zh = zr + half * 68;          // padded half offset
            #pragma unroll
            for (int u = 0; u < 16; u++) {
                ulonglong2 zz = *(const ulonglong2*)(zh + 4 * u);
                aS = add2(aS, add2(zz.x, zz.y));
                aQ = fma2(zz.x, zz.x, aQ);
                aQ = fma2(zz.y, zz.y, aQ);
                int p = half * 32 + 2 * u;
                const ulonglong2* w0 = (const ulonglong2*)&wq[p * NH];
                const ulonglong2* w1 = (const ulonglong2*)&wq[(p + 1) * NH];
                #pragma unroll
                for (int q2 = 0; q2 < 4; q2++) {
                    ulonglong2 wa = w0[q2];
                    ulonglong2 wb = w1[q2];
                    aD[2 * q2]     = fma2(zz.x, wa.x, aD[2 * q2]);
                    aD[2 * q2 + 1] = fma2(zz.x, wa.y, aD[2 * q2 + 1]);
                    aD[2 * q2]     = fma2(zz.y, wb.x, aD[2 * q2]);
                    aD[2 * q2 + 1] = fma2(zz.y, wb.y, aD[2 * q2 + 1]);
                }
            }
        }

        float2 dS = unpk2(aS), dQ = unpk2(aQ);
        float s  = dS.x + dS.y;
        float qq = dQ.x + dQ.y;
        float mu  = s * (1.0f / CZ);
        float var = qq * (1.0f / CZ) - mu * mu;
        float rs  = rsqrtf(var + 1e-5f);

        size_t j = (size_t)(jb + tt * BT_ROWS + tid);
        #pragma unroll
        for (int h = 0; h < NH; h++) {
            float2 dd = unpk2(aD[h]);
            float dot = dd.x + dd.y;
            float bv = rs * (dot - mu * s_cs[h]) + s_cb[h];
            g_bias[((size_t)h * R + i) * R + j] = bv;
        }
        __syncthreads();   // zs safe for reuse by next tile's loads

        if (tt + 1 < BT_TILES) {
            const float* src = zstrip + (size_t)(tt + 1) * BT_ROWS * CZ;
            #pragma unroll
            for (int k = 0; k < 32; k++) {
                int idx = tid + k * 64;
                int row = idx >> 5, s4 = idx & 31;
                uint32_t dw = (uint32_t)(row * BT_STRIDE + s4 * 4 + ((s4 >= 16) ? 4 : 0));
                cpa16(zs_base + dw * 4, src + row * CZ + s4 * 4);
            }
            cpa_commit();
        }
    }
}

// ---------------------------------------------------------------------------
// K4: flash attention with additive bias, SPLIT over j (NSPLIT=8).
// grid (16 q-tiles, 8 heads, 8 j-splits), 256 threads; 128 j per block.
// ---------------------------------------------------------------------------
__global__ void k_attn() {
    int h   = blockIdx.y;
    int q0  = blockIdx.x * 64;
    int zsp = blockIdx.z;
    int tid = threadIdx.x;
    int tr = tid >> 4, tc = tid & 15;

    __shared__ float qT[32][72];
    __shared__ float kT[32][72];
    __shared__ float vs[64][36];
    __shared__ float ps[64][68];
    __shared__ float m_s[64], l_s[64], f_s[64];

    #pragma unroll
    for (int t = 0; t < 8; t++) {
        int idx = tid + t * 256;
        int r = idx >> 5, d = idx & 31;
        qT[d][r] = g_q[(q0 + r) * HD + h * CHID + d];
    }
    if (tid < 64) { m_s[tid] = -1e30f; l_s[tid] = 0.f; }

    float o[4][2] = {};

    for (int jt = 0; jt < 2; jt++) {
        int j0 = zsp * 128 + jt * 64;
        __syncthreads();
        #pragma unroll
        for (int t = 0; t < 8; t++) {
            int idx = tid + t * 256;
            int r = idx >> 5, d = idx & 31;
            kT[d][r] = g_k[(j0 + r) * HD + h * CHID + d];
            vs[r][d] = g_v[(j0 + r) * HD + h * CHID + d];
        }
        __syncthreads();

        float s[4][4];
        #pragma unroll
        for (int rr = 0; rr < 4; rr++) {
            float4 b4 = *(const float4*)&g_bias[((size_t)h * R + q0 + 4 * tr + rr) * R + j0 + 4 * tc];
            s[rr][0] = b4.x; s[rr][1] = b4.y; s[rr][2] = b4.z; s[rr][3] = b4.w;
        }
        #pragma unroll
        for (int kk = 0; kk < 32; kk++) {
            float4 a4 = *(const float4*)&qT[kk][4 * tr];
            float4 b4 = *(const float4*)&kT[kk][4 * tc];
            float av[4] = {a4.x, a4.y, a4.z, a4.w};
            float bv[4] = {b4.x, b4.y, b4.z, b4.w};
            #pragma unroll
            for (int rr = 0; rr < 4; rr++)
                #pragma unroll
                for (int cc = 0; cc < 4; cc++)
                    s[rr][cc] += av[rr] * bv[cc];
        }
        #pragma unroll
        for (int rr = 0; rr < 4; rr++)
            *(float4*)&ps[4 * tr + rr][4 * tc] =
                make_float4(s[rr][0], s[rr][1], s[rr][2], s[rr][3]);
        __syncthreads();

        {
            int row = tid >> 2, p = tid & 3;
            float mo = m_s[row];
            float mc = -1e30f;
            #pragma unroll
            for (int c = 0; c < 16; c += 4) {
                float4 v = *(const float4*)&ps[row][p * 16 + c];
                mc = fmaxf(mc, fmaxf(fmaxf(v.x, v.y), fmaxf(v.z, v.w)));
            }
            mc = fmaxf(mc, __shfl_xor_sync(0xffffffffu, mc, 1));
            mc = fmaxf(mc, __shfl_xor_sync(0xffffffffu, mc, 2));
            float mn2 = fmaxf(mo, mc);
            float l = 0.f;
            #pragma unroll
            for (int c = 0; c < 16; c += 4) {
                float4 v = *(const float4*)&ps[row][p * 16 + c];
                v.x = __expf(v.x - mn2); v.y = __expf(v.y - mn2);
                v.z = __expf(v.z - mn2); v.w = __expf(v.w - mn2);
                *(float4*)&ps[row][p * 16 + c] = v;
                l += v.x + v.y + v.z + v.w;
            }
            l += __shfl_xor_sync(0xffffffffu, l, 1);
            l += __shfl_xor_sync(0xffffffffu, l, 2);
            if (p == 0) {
                float f = __expf(mo - mn2);
                f_s[row] = f;
                l_s[row] = l_s[row] * f + l;
                m_s[row] = mn2;
            }
        }
        __syncthreads();

        float fr[4];
        #pragma unroll
        for (int rr = 0; rr < 4; rr++) fr[rr] = f_s[4 * tr + rr];
        #pragma unroll
        for (int rr = 0; rr < 4; rr++) { o[rr][0] *= fr[rr]; o[rr][1] *= fr[rr]; }

        #pragma unroll
        for (int j = 0; j < 64; j += 4) {
            float4 pv[4];
            #pragma unroll
            for (int rr = 0; rr < 4; rr++)
                pv[rr] = *(const float4*)&ps[4 * tr + rr][j];
            float2 vv[4];
            #pragma unroll
            for (int e = 0; e < 4; e++)
                vv[e] = *(const float2*)&vs[j + e][2 * tc];
            #pragma unroll
            for (int rr = 0; rr < 4; rr++) {
                o[rr][0] += pv[rr].x * vv[0].x; o[rr][1] += pv[rr].x * vv[0].y;
                o[rr][0] += pv[rr].y * vv[1].x; o[rr][1] += pv[rr].y * vv[1].y;
                o[rr][0] += pv[rr].z * vv[2].x; o[rr][1] += pv[rr].z * vv[2].y;
                o[rr][0] += pv[rr].w * vv[3].x; o[rr][1] += pv[rr].w * vv[3].y;
            }
        }
    }

    int base = (zsp * NH + h) * R + q0;
    #pragma unroll
    for (int rr = 0; rr < 4; rr++) {
        g_po[(size_t)(base + 4 * tr + rr) * CHID + 2 * tc + 0] = o[rr][0];
        g_po[(size_t)(base + 4 * tr + rr) * CHID + 2 * tc + 1] = o[rr][1];
    }
    __syncthreads();
    if (tid < 64) {
        g_pm[base + tid] = m_s[tid];
        g_pl[base + tid] = l_s[tid];
    }
}

// ---------------------------------------------------------------------------
// K4b: merge split-j partials -> g_o
// ---------------------------------------------------------------------------
__global__ void k_merge() {
    int idx = blockIdx.x * 256 + threadIdx.x;      // over NH*R*CHID = 262144
    int d = idx & (CHID - 1);
    int q = (idx >> 5) & (R - 1);
    int h = idx >> 15;

    float mv[NSPLIT];
    float M = -1e30f;
    #pragma unroll
    for (int s2 = 0; s2 < NSPLIT; s2++) {
        mv[s2] = g_pm[(s2 * NH + h) * R + q];
        M = fmaxf(M, mv[s2]);
    }
    float L = 0.f, ov = 0.f;
    #pragma unroll
    for (int s2 = 0; s2 < NSPLIT; s2++) {
        float e = __expf(mv[s2] - M);
        L  += g_pl[(s2 * NH + h) * R + q] * e;
        ov += g_po[(size_t)((s2 * NH + h) * R + q) * CHID + d] * e;
    }
    g_o[q * HD + h * CHID + d] = ov / L;
}

// ---------------------------------------------------------------------------
// K5: out = (o * sigmoid(gw)) @ Wo + bo
// ---------------------------------------------------------------------------
__global__ void k_out(const float* __restrict__ Wo,
                      const float* __restrict__ bo,
                      float* __restrict__ out) {
    int r0 = blockIdx.y * 64, c0 = blockIdx.x * 64;
    __shared__ float As[32][72];
    __shared__ float Bs[32][72];
    int tid = threadIdx.x;
    int tr = tid >> 4, tc = tid & 15;
    float acc[4][4] = {};

    for (int k0 = 0; k0 < HD; k0 += 32) {
        #pragma unroll
        for (int t = 0; t < 8; t++) {
            int idx = tid + t * 256;
            int r = idx >> 5, kk = idx & 31;
            int gi = (r0 + r) * HD + k0 + kk;
            float gate = 1.0f / (1.0f + __expf(-g_gw[gi]));
            As[kk][r] = g_o[gi] * gate;
        }
        #pragma unroll
        for (int t = 0; t < 8; t++) {
            int idx = tid + t * 256;
            int kk = idx >> 6, cc = idx & 63;
            Bs[kk][cc] = Wo[(k0 + kk) * CIN + c0 + cc];
        }
        __syncthreads();
        #pragma unroll
        for (int kk = 0; kk < 32; kk++) {
            float4 a4 = *(const float4*)&As[kk][4 * tr];
            float4 b4 = *(const float4*)&Bs[kk][4 * tc];
            float av[4] = {a4.x, a4.y, a4.z, a4.w};
            float bv[4] = {b4.x, b4.y, b4.z, b4.w};
            #pragma unroll
            for (int rr = 0; rr < 4; rr++)
                #pragma unroll
                for (int cc = 0; cc < 4; cc++)
                    acc[rr][cc] += av[rr] * bv[cc];
        }
        __syncthreads();
    }
    #pragma unroll
    for (int rr = 0; rr < 4; rr++) {
        int c = c0 + 4 * tc;
        float4 o4 = make_float4(acc[rr][0] + bo[c + 0], acc[rr][1] + bo[c + 1],
                                acc[rr][2] + bo[c + 2], acc[rr][3] + bo[c + 3]);
        *(float4*)&out[(r0 + 4 * tr + rr) * CIN + c] = o4;
    }
}

// ---------------------------------------------------------------------------
extern "C" void kernel_launch(void* const* d_in, const int* in_sizes, int n_in,
                              void* d_out, int out_size) {
    const float* m      = (const float*)d_in[0];
    const float* z      = (const float*)d_in[1];
    const float* ln_m_w = (const float*)d_in[2];
    const float* ln_m_b = (const float*)d_in[3];
    const float* ln_z_w = (const float*)d_in[4];
    const float* ln_z_b = (const float*)d_in[5];
    const float* Wz     = (const float*)d_in[6];
    const float* Wq     = (const float*)d_in[7];
    const float* Wk     = (const float*)d_in[8];
    const float* Wv     = (const float*)d_in[9];
    const float* Wg     = (const float*)d_in[10];
    // d_in[11] = bg (unused by reference)
    const float* Wo     = (const float*)d_in[12];
    const float* bo     = (const float*)d_in[13];
    float* out = (float*)d_out;

    // One-time stream/event creation (first call is the uncaptured
    // correctness run; reused verbatim during graph capture).
    static cudaStream_t s2 = nullptr;
    static cudaEvent_t eFork = nullptr, eJoin = nullptr;
    if (s2 == nullptr) {
        cudaStreamCreateWithFlags(&s2, cudaStreamNonBlocking);
        cudaEventCreateWithFlags(&eFork, cudaEventDisableTiming);
        cudaEventCreateWithFlags(&eJoin, cudaEventDisableTiming);
    }

    // Fork: side stream runs the mn chain while main stream runs prep+bias.
    cudaEventRecord(eFork, 0);
    cudaStreamWaitEvent(s2, eFork, 0);

    // main stream: prep -> bias (DRAM-bound, ~108us)
    k_prep<<<1, 256>>>(ln_z_w, ln_z_b, Wz);
    k_bias<<<dim3(4, R), 64>>>(z);

    // side stream: lnm -> qkvg (compute-bound, ~20us, fully hidden)
    k_lnm<<<R, 256, 0, s2>>>(m, ln_m_w, ln_m_b);
    k_qkvg<<<dim3(4, 16, 4), 256, 0, s2>>>(Wq, Wk, Wv, Wg);

    // Join: attention needs bias + q/k/v.
    cudaEventRecord(eJoin, s2);
    cudaStreamWaitEvent(0, eJoin, 0);

    k_attn<<<dim3(16, NH, NSPLIT), 256>>>();
    k_merge<<<NH * R * CHID / 256, 256>>>();
    k_out<<<dim3(4, 16), 256>>>(Wo, bo, out);
}